// round 12
// baseline (speedup 1.0000x reference)
#include <cuda_runtime.h>
#include <cuda_fp16.h>
#include <cstdint>

#define NN   10000
#define EE   320000
#define RR   460
#define BB   30
#define DD   200
#define KTOT 6200
#define KPAD 6208            // multiple of 64
#define MPAD 10112           // 79 * 128
#define NPAD 224
#define NCHTOT 194           // KPAD / 32
#define NKSL  16
#define NMT   79
#define NUNITS (NMT * NKSL)

// ---- device scratch (zero-initialized; pads never written -> stay 0) ----
__device__ __align__(256) __half g_Ah[(size_t)MPAD * KPAD];
__device__ __align__(256) __half g_Bh[(size_t)NPAD * KPAD];   // B^T: n-major rows, k cols
__device__ __align__(256) __half g_Xh[(size_t)NN * DD];       // x in fp16
__device__ __align__(256) __half g_Crh[(RR + 1) * 32];        // coeff fp16, row RR = zeros
__device__ int g_deg[NN];
__device__ int g_off[NN + 1];
__device__ int g_cur[NN];
__device__ int g_esrc[EE];
__device__ int g_erel[EE];

// ---------------- helpers ----------------
__device__ __forceinline__ uint32_t smem_u32(const void* p) {
    uint32_t a;
    asm("{ .reg .u64 t; cvta.to.shared.u64 t, %1; cvt.u32.u64 %0, t; }" : "=r"(a) : "l"(p));
    return a;
}
__device__ __forceinline__ void ldsm4(uint32_t* r, uint32_t a) {
    asm volatile("ldmatrix.sync.aligned.m8n8.x4.shared.b16 {%0,%1,%2,%3}, [%4];"
                 : "=r"(r[0]), "=r"(r[1]), "=r"(r[2]), "=r"(r[3]) : "r"(a));
}
__device__ __forceinline__ void ldsm4t(uint32_t* r, uint32_t a) {
    asm volatile("ldmatrix.sync.aligned.m8n8.x4.trans.shared.b16 {%0,%1,%2,%3}, [%4];"
                 : "=r"(r[0]), "=r"(r[1]), "=r"(r[2]), "=r"(r[3]) : "r"(a));
}
__device__ __forceinline__ void mma16816(float* c, const uint32_t* a, uint32_t b0, uint32_t b1) {
    asm volatile(
        "mma.sync.aligned.m16n8k16.row.col.f32.f16.f16.f32 "
        "{%0,%1,%2,%3}, {%4,%5,%6,%7}, {%8,%9}, {%0,%1,%2,%3};"
        : "+f"(c[0]), "+f"(c[1]), "+f"(c[2]), "+f"(c[3])
        : "r"(a[0]), "r"(a[1]), "r"(a[2]), "r"(a[3]), "r"(b0), "r"(b1));
}
__device__ __forceinline__ void cpasync16(uint32_t sa, const void* gp) {
    asm volatile("cp.async.cg.shared.global [%0], [%1], 16;" :: "r"(sa), "l"(gp));
}

// ---------------- CSR build ----------------
__global__ void k_count(const int* __restrict__ eidx) {
    int e = blockIdx.x * blockDim.x + threadIdx.x;
    if (e < EE) atomicAdd(&g_deg[eidx[EE + e]], 1);
}
__global__ void k_scan() {
    __shared__ int part[256];
    int t = threadIdx.x;
    const int PER = 40;
    int base = t * PER;
    int s = 0;
    for (int i = 0; i < PER; i++) {
        int idx = base + i;
        if (idx < NN) s += g_deg[idx];
    }
    part[t] = s;
    __syncthreads();
    for (int off = 1; off < 256; off <<= 1) {
        int v = (t >= off) ? part[t - off] : 0;
        __syncthreads();
        part[t] += v;
        __syncthreads();
    }
    int run = (t == 0) ? 0 : part[t - 1];
    for (int i = 0; i < PER; i++) {
        int idx = base + i;
        if (idx < NN) {
            g_off[idx] = run;
            g_cur[idx] = run;
            run += g_deg[idx];
        }
    }
    if (t == 255) g_off[NN] = part[255];
}

// ---------------- fused: fill + W transpose + out zero + x->fp16 + coeff->fp16 ----------------
#define NB_FILL 1250
#define NB_W    1358         // (KPAD/32) * 7
#define NB_O    7813         // ceil(NN*DD/256)
#define NB_X    7813         // ceil(NN*DD/256)
#define NB_C    54           // ceil(RR*BB/256)
__global__ void k_misc(const int* __restrict__ eidx, const int* __restrict__ etype,
                       const float* __restrict__ w, const float* __restrict__ sw,
                       const float* __restrict__ x, const float* __restrict__ coeff,
                       float* __restrict__ out) {
    int bw = blockIdx.x, tid = threadIdx.x;
    if (bw < NB_FILL) {
        int e = bw * 256 + tid;
        if (e < EE) {
            int t = eidx[EE + e];
            int p = atomicAdd(&g_cur[t], 1);
            g_esrc[p] = eidx[e];
            g_erel[p] = etype[e];
        }
    } else if (bw < NB_FILL + NB_W) {
        __shared__ float tile[32][33];
        int b = bw - NB_FILL;
        int k0 = (b % 194) * 32;
        int n0 = (b / 194) * 32;
        int tx = tid & 31, ty = tid >> 5;
#pragma unroll
        for (int s = 0; s < 4; s++) {
            int k = k0 + ty + 8 * s;
            int n = n0 + tx;
            float v = 0.f;
            if (n < DD) {
                if (k < 6000)      v = w[(size_t)k * DD + n];
                else if (k < KTOT) v = sw[(size_t)(k - 6000) * DD + n];
            }
            tile[ty + 8 * s][tx] = v;
        }
        __syncthreads();
#pragma unroll
        for (int s = 0; s < 4; s++) {
            int n = n0 + ty + 8 * s;
            int k = k0 + tx;
            if (n < DD) g_Bh[(size_t)n * KPAD + k] = __float2half(tile[tx][ty + 8 * s]);
        }
    } else if (bw < NB_FILL + NB_W + NB_O) {
        int i = (bw - NB_FILL - NB_W) * 256 + tid;
        if (i < NN * DD) out[i] = 0.f;
    } else if (bw < NB_FILL + NB_W + NB_O + NB_X) {
        int i = (bw - NB_FILL - NB_W - NB_O) * 256 + tid;
        if (i < NN * DD) g_Xh[i] = __float2half(x[i]);
    } else {
        int i = (bw - NB_FILL - NB_W - NB_O - NB_X) * 256 + tid;
        if (i < RR * BB) {
            int r = i / BB, b = i - r * BB;
            g_Crh[r * 32 + b] = __float2half(coeff[i]);
        }
    }
}

// ---------------- tensor-core aggregation (fp16 1-term) ----------------
// Per node: H^T(208x32) = Xg^T(208 x deg) @ Cg(deg x 32), fp32 accum.
// 32-edge chunks; pad edges use coeff row RR (zeros) so contributions vanish.
// X rows over-staged to 512B (shift-only addressing); garbage lands only in
// d>=200 outputs which the epilogue never stores.
#define AT   128
#define ECH  32
#define RSX  528              // 512 + 16 pad; 528 % 128 = 16 -> conflict-free ldsm
#define XBUF (ECH * RSX)      // 16896
#define RSC  80
#define CBUF (ECH * RSC)      // 2560

__global__ __launch_bounds__(AT) void k_agg() {
    __shared__ __align__(16) char sX[2][XBUF];
    __shared__ __align__(16) char sC[2][CBUF];
    __shared__ int sSrc[2][ECH], sRel[2][ECH];
    uint32_t sxa = smem_u32(sX), sca = smem_u32(sC);
    int tid = threadIdx.x, lane = tid & 31, w = tid >> 5;
    int n = blockIdx.x;
    int start = g_off[n], end = g_off[n + 1];
    int deg = end - start;
    float inv = 1.0f / (float)(deg > 1 ? deg : 1);
    int chunks = (deg + ECH - 1) >> 5;
    int mtcnt = (w == 3) ? 4 : 3;     // 13 m-tiles over 4 warps: 3,3,3,4

    float acc[4][4][4];
#pragma unroll
    for (int i = 0; i < 4; i++)
#pragma unroll
        for (int j = 0; j < 4; j++)
#pragma unroll
            for (int q = 0; q < 4; q++) acc[i][j][q] = 0.f;

    auto meta = [&](int c, int buf) {
        if (tid < ECH) {
            int e = start + c * ECH + tid;
            if (e < end) { sSrc[buf][tid] = g_esrc[e]; sRel[buf][tid] = g_erel[e]; }
            else         { sSrc[buf][tid] = 0;         sRel[buf][tid] = RR; }
        }
    };
    auto issue = [&](int buf) {
        const char* xp = (const char*)g_Xh;
        const char* cp = (const char*)g_Crh;
#pragma unroll
        for (int i = 0; i < 9; i++) {         // 1152 ops = 9 * 128 exactly
            int t = tid + i * AT;
            if (t < 1024) {                   // X: 32 rows x 32 x 16B (512B/row)
                int r = t >> 5, q = t & 31;
                cpasync16(sxa + buf * XBUF + r * RSX + q * 16,
                          xp + (size_t)sSrc[buf][r] * 400 + q * 16);
            } else {                          // C: 32 rows x 4 x 16B
                int t2 = t - 1024;
                int r = t2 >> 2, q = t2 & 3;
                cpasync16(sca + buf * CBUF + r * RSC + q * 16,
                          cp + (size_t)sRel[buf][r] * 64 + q * 16);
            }
        }
        asm volatile("cp.async.commit_group;");
    };

    if (chunks > 0) {
        meta(0, 0);
        __syncthreads();
        issue(0);

        int j = lane >> 3;
        int rowA = (lane & 7) + (j >> 1) * 8;
        int cbA  = (j & 1) * 16;
        int rowB = (lane & 7) + (j & 1) * 8;
        int cbB  = (j >> 1) * 16;

        for (int c = 0; c < chunks; c++) {
            int buf = c & 1;
            if (c + 1 < chunks) {
                meta(c + 1, buf ^ 1);
                __syncthreads();              // meta visible; prev compute done
                issue(buf ^ 1);
                asm volatile("cp.async.wait_group 1;");
            } else {
                asm volatile("cp.async.wait_group 0;");
            }
            __syncthreads();                  // chunk c data visible

#pragma unroll
            for (int ks = 0; ks < 2; ks++) {
                uint32_t bh[2][4];
                uint32_t bbase = sca + buf * CBUF + (rowB + 16 * ks) * RSC + cbB;
                ldsm4t(bh[0], bbase);         // n-tiles 0,1
                ldsm4t(bh[1], bbase + 32);    // n-tiles 2,3
#pragma unroll
                for (int mtl = 0; mtl < 4; mtl++) {
                    if (mtl >= mtcnt) break;
                    int mt = 3 * w + mtl;
                    uint32_t ah[4];
                    ldsm4t(ah, sxa + buf * XBUF + (rowA + 16 * ks) * RSX + mt * 32 + cbA);
#pragma unroll
                    for (int nt = 0; nt < 4; nt++)
                        mma16816(acc[mtl][nt], ah,
                                 bh[nt >> 1][(nt & 1) * 2], bh[nt >> 1][(nt & 1) * 2 + 1]);
                }
            }
        }
    }

    // epilogue: scale by inv, store fp16 into g_Ah row n (d<200, b<30 only)
    size_t rowb = (size_t)n * KPAD;
#pragma unroll
    for (int mtl = 0; mtl < 4; mtl++) {
        if (mtl >= mtcnt) break;
        int mt = 3 * w + mtl;
        int d0 = mt * 16 + (lane >> 2);
#pragma unroll
        for (int nt = 0; nt < 4; nt++) {
            int b0 = nt * 8 + (lane & 3) * 2;
#pragma unroll
            for (int q = 0; q < 4; q++) {
                int d = d0 + (q >> 1) * 8;
                int b = b0 + (q & 1);
                if (b < BB && d < DD)
                    g_Ah[rowb + b * DD + d] = __float2half(acc[mtl][nt][q] * inv);
            }
        }
    }
    if (tid < 25)   // self-loop K-columns 6000..6199 (copy fp16 x row, 400B)
        ((uint4*)(g_Ah + rowb + 6000))[tid] = ((const uint4*)(g_Xh + (size_t)n * DD))[tid];
}

// ---------------- persistent fp16 1-term MMA GEMM (unchanged from R10) ----------------
#define GT     256
#define RS     80
#define A_ARR  10240
#define B_ARR  17920
#define OFF_B  10240
#define STAGE  28160
#define SMEM_G (2 * STAGE)
#define GRID_G 152

__global__ __launch_bounds__(GT, 1) void k_gemm(const float* __restrict__ bias,
                                                float* __restrict__ out) {
    extern __shared__ char smem[];
    uint32_t sb = smem_u32(smem);
    int tid = threadIdx.x, lane = tid & 31, wid = tid >> 5;
    int wm = wid & 3, wn = wid >> 2;

    const char* gA = (const char*)g_Ah;
    const char* gB = (const char*)g_Bh;

    int ri = lane & 7, mi = lane >> 3;
    uint32_t aOff = (uint32_t)((wm * 32 + ri + (mi & 1) * 8) * RS + (mi >> 1) * 16);
    uint32_t bOff = (uint32_t)(OFF_B + (wn * 112 + ri + ((mi >> 1) & 1) * 8) * RS + (mi & 1) * 16);
    int g = lane >> 2, tg = lane & 3;

    for (int u = blockIdx.x; u < NUNITS; u += GRID_G) {
        int mt = u % NMT;
        int ks = u / NMT;
        int m0 = mt * 128;
        int c0 = (NCHTOT * ks) >> 4;
        int c1 = (NCHTOT * (ks + 1)) >> 4;

        float acc[2][14][4];
#pragma unroll
        for (int i = 0; i < 2; i++)
#pragma unroll
            for (int jj = 0; jj < 14; jj++)
#pragma unroll
                for (int q = 0; q < 4; q++) acc[i][jj][q] = 0.f;

        auto issue = [&](int c, int buf) {
            uint32_t st = sb + buf * STAGE;
            size_t kb2 = (size_t)c * 64;
#pragma unroll
            for (int i = 0; i < 6; i++) {
                int t = tid + i * GT;
                if (t < 1408) {
                    uint32_t sa;
                    const char* gp;
                    if (t < 512) {
                        int r = t >> 2, q = t & 3;
                        sa = st + r * RS + q * 16;
                        gp = gA + (size_t)(m0 + r) * (KPAD * 2) + kb2 + q * 16;
                    } else {
                        int t2 = t - 512;
                        int r = t2 >> 2, q = t2 & 3;
                        sa = st + OFF_B + r * RS + q * 16;
                        gp = gB + (size_t)r * (KPAD * 2) + kb2 + q * 16;
                    }
                    cpasync16(sa, gp);
                }
            }
            asm volatile("cp.async.commit_group;");
        };

        issue(c0, 0);
        for (int c = c0; c < c1; c++) {
            int buf = (c - c0) & 1;
            if (c + 1 < c1) {
                issue(c + 1, buf ^ 1);
                asm volatile("cp.async.wait_group 1;");
            } else {
                asm volatile("cp.async.wait_group 0;");
            }
            __syncthreads();

            uint32_t st = sb + buf * STAGE;
#pragma unroll
            for (int kk = 0; kk < 2; kk++) {
                uint32_t ka = st + aOff + kk * 32;
                uint32_t ah0[4], ah1[4];
                ldsm4(ah0, ka);
                ldsm4(ah1, ka + 16 * RS);
                uint32_t kb = st + bOff + kk * 32;
#pragma unroll
                for (int nf = 0; nf < 7; nf++) {
                    uint32_t bh[4];
                    ldsm4(bh, kb + nf * (16 * RS));
                    mma16816(acc[0][2 * nf],     ah0, bh[0], bh[1]);
                    mma16816(acc[1][2 * nf],     ah1, bh[0], bh[1]);
                    mma16816(acc[0][2 * nf + 1], ah0, bh[2], bh[3]);
                    mma16816(acc[1][2 * nf + 1], ah1, bh[2], bh[3]);
                }
            }
            __syncthreads();
        }

#pragma unroll
        for (int mf = 0; mf < 2; mf++) {
            int r0 = m0 + wm * 32 + mf * 16 + g;
            int r1 = r0 + 8;
#pragma unroll
            for (int nf = 0; nf < 14; nf++) {
                int col = wn * 112 + nf * 8 + tg * 2;
                if (col < DD) {
                    float b0 = 0.f, b1 = 0.f;
                    if (ks == 0) { b0 = bias[col]; b1 = bias[col + 1]; }
                    if (r0 < NN) {
                        atomicAdd(&out[(size_t)r0 * DD + col],     acc[mf][nf][0] + b0);
                        atomicAdd(&out[(size_t)r0 * DD + col + 1], acc[mf][nf][1] + b1);
                    }
                    if (r1 < NN) {
                        atomicAdd(&out[(size_t)r1 * DD + col],     acc[mf][nf][2] + b0);
                        atomicAdd(&out[(size_t)r1 * DD + col + 1], acc[mf][nf][3] + b1);
                    }
                }
            }
        }
    }
}

extern "C" void kernel_launch(void* const* d_in, const int* in_sizes, int n_in,
                              void* d_out, int out_size) {
    const float* x      = (const float*)d_in[0];
    const float* weight = (const float*)d_in[1];
    const float* coeff  = (const float*)d_in[2];
    const float* selfw  = (const float*)d_in[3];
    const float* bias   = (const float*)d_in[4];
    const int*   eidx   = (const int*)d_in[5];
    const int*   etype  = (const int*)d_in[6];
    float*       out    = (float*)d_out;

    static void* p_deg = nullptr;
    if (!p_deg) {
        cudaGetSymbolAddress(&p_deg, g_deg);
        cudaFuncSetAttribute(k_gemm, cudaFuncAttributeMaxDynamicSharedMemorySize, SMEM_G);
    }

    cudaMemsetAsync(p_deg, 0, NN * sizeof(int));
    k_count<<<(EE + 255) / 256, 256>>>(eidx);
    k_scan<<<1, 256>>>();
    k_misc<<<NB_FILL + NB_W + NB_O + NB_X + NB_C, 256>>>(eidx, etype, weight, selfw, x, coeff, out);
    k_agg<<<NN, AT>>>();
    k_gemm<<<GRID_G, GT, SMEM_G>>>(bias, out);
}